// round 16
// baseline (speedup 1.0000x reference)
#include <cuda_runtime.h>

#define Hc 2048
#define Wc 2048
#define UH 2049
#define UW 2048
#define VH 2048
#define VW 2049
#define DT 0.01f
#define VISC 0.001f

// Device scratch
__device__ float g_u  [UH * UW];
__device__ float g_v  [VH * VW];
__device__ float g_dens[Hc * Wc];
__device__ float g_div [Hc * Wc];
__device__ float g_p  [Hc * Wc];
__device__ float g_p2 [Hc * Wc];

// ================= fused diffuse (u | v+force | dens) =================
__device__ __forceinline__ void diffuse_f4_body(const float* __restrict__ f,
                                                float* __restrict__ out,
                                                int h, int w, float a,
                                                int qx, int i) {
    int w4 = w >> 2;
    if (i >= h || qx >= w4) return;
    int j0 = qx * 4;
    const float4* f4 = (const float4*)f;
    float4 c  = f4[i * w4 + qx];
    int iu = max(i - 1, 0), id = min(i + 1, h - 1);
    float4 up = f4[iu * w4 + qx];
    float4 dn = f4[id * w4 + qx];
    float lf = (j0 > 0)       ? f[i * w + j0 - 1] : c.x;
    float rt = (j0 + 4 < w)   ? f[i * w + j0 + 4] : c.w;
    float4 r;
    r.x = c.x + a * (up.x + dn.x + lf  + c.y - 4.0f * c.x);
    r.y = c.y + a * (up.y + dn.y + c.x + c.z - 4.0f * c.y);
    r.z = c.z + a * (up.z + dn.z + c.y + c.w - 4.0f * c.z);
    r.w = c.w + a * (up.w + dn.w + c.z + rt  - 4.0f * c.w);
    ((float4*)out)[i * w4 + qx] = r;
}

__device__ __forceinline__ float vfrc(const float* __restrict__ v,
                                      const float* __restrict__ dens,
                                      int i, int j) {
    float val = v[i * VW + j];
    if (j < Wc) val += (DT * 0.1f) * dens[i * Wc + j];
    return val;
}

__device__ __forceinline__ float4 vfrc4s(const float* __restrict__ v,
                                         const float* __restrict__ dens,
                                         int i, int j0) {
    const float* vr = &v[i * VW + j0];
    float4 val = make_float4(vr[0], vr[1], vr[2], vr[3]);
    float4 dd  = *(const float4*)&dens[i * Wc + j0];
    val.x += (DT * 0.1f) * dd.x;
    val.y += (DT * 0.1f) * dd.y;
    val.z += (DT * 0.1f) * dd.z;
    val.w += (DT * 0.1f) * dd.w;
    return val;
}

__global__ void diffuse_all_kernel(const float* __restrict__ u_in,
                                   const float* __restrict__ v_in,
                                   const float* __restrict__ dens_in,
                                   float* __restrict__ u_out,
                                   float* __restrict__ v_out,
                                   float* __restrict__ dens_out) {
    int qx = blockIdx.x * blockDim.x + threadIdx.x;
    int i  = blockIdx.y * blockDim.y + threadIdx.y;
    int z  = blockIdx.z;
    const float a  = DT * VISC;
    const float ad = DT * VISC * 0.1f;

    if (z == 0) {
        diffuse_f4_body(u_in, u_out, UH, UW, a, qx, i);
    } else if (z == 2) {
        diffuse_f4_body(dens_in, dens_out, Hc, Wc, ad, qx, i);
    } else {
        if (i >= VH || qx >= 512) return;
        int j0 = qx * 4;
        int iu = max(i - 1, 0), id = min(i + 1, VH - 1);
        float4 c  = vfrc4s(v_in, dens_in, i, j0);
        float4 up = vfrc4s(v_in, dens_in, iu, j0);
        float4 dn = vfrc4s(v_in, dens_in, id, j0);
        float lf = (j0 > 0) ? vfrc(v_in, dens_in, i, j0 - 1) : c.x;
        float rt = vfrc(v_in, dens_in, i, j0 + 4);
        float4 r;
        r.x = c.x + a * (up.x + dn.x + lf  + c.y - 4.0f * c.x);
        r.y = c.y + a * (up.y + dn.y + c.x + c.z - 4.0f * c.y);
        r.z = c.z + a * (up.z + dn.z + c.y + c.w - 4.0f * c.z);
        r.w = c.w + a * (up.w + dn.w + c.z + rt  - 4.0f * c.w);
        float* vo = &v_out[i * VW + j0];
        vo[0] = r.x; vo[1] = r.y; vo[2] = r.z; vo[3] = r.w;
        if (qx == 511) {
            int j = 2048;
            float cc = v_in[i * VW + j];
            float u2 = v_in[iu * VW + j];
            float d2 = v_in[id * VW + j];
            float l2 = vfrc(v_in, dens_in, i, j - 1);
            v_out[i * VW + j] = cc + a * (u2 + d2 + l2 + cc - 4.0f * cc);
        }
    }
}

// ---- divergence ----
__global__ void div_f4_kernel(const float* __restrict__ u, const float* __restrict__ v,
                              float* __restrict__ dv) {
    int qx = blockIdx.x * blockDim.x + threadIdx.x;
    int i  = blockIdx.y * blockDim.y + threadIdx.y;
    int w4 = Wc >> 2;
    if (i >= Hc || qx >= w4) return;
    int j0 = qx * 4;
    const float4* u4 = (const float4*)u;
    float4 u0 = u4[i * w4 + qx];
    float4 u1 = u4[(i + 1) * w4 + qx];
    const float* vr = v + i * VW + j0;
    float v0 = vr[0], v1 = vr[1], v2 = vr[2], v3 = vr[3], v4 = vr[4];
    float4 r;
    r.x = (u1.x - u0.x + v1 - v0) / DT;
    r.y = (u1.y - u0.y + v2 - v1) / DT;
    r.z = (u1.z - u0.z + v3 - v2) / DT;
    r.w = (u1.w - u0.w + v4 - v3) / DT;
    ((float4*)dv)[i * w4 + qx] = r;
}

// ============ fused 4x Jacobi: WIDE register strips (8 cols x 4 rows/thread) ============
// Block (8,16) = 128 threads, tile 64x64, output 56x56. Shfl width 8:
// only 2 shfl per 8 points per iteration (half of the narrow version).
#define OT 56

__device__ __forceinline__ float gload(const float* __restrict__ p, int gy, int gx) {
    return (gy >= 0 && gy < Hc && gx >= 0 && gx < Wc) ? p[gy * Wc + gx] : 0.0f;
}

__global__ void __launch_bounds__(128)
jacobiW_kernel(const float* __restrict__ pin, const float* __restrict__ dv,
               float* __restrict__ pout, int p_zero) {
    __shared__ float4 sTA[16][9], sTB[16][9];
    __shared__ float4 sBA[16][9], sBB[16][9];

    const int tx = threadIdx.x;              // 0..7  (8-col pairs)
    const int ty = threadIdx.y;              // 0..15 (4-row strips)
    const int bx0 = blockIdx.x * OT - 4;
    const int by0 = blockIdx.y * OT - 4;
    const int gx0 = bx0 + tx * 8;
    const int gyBase = by0 + ty * 4;
    const bool border = (blockIdx.x == 0 || blockIdx.y == 0 ||
                         blockIdx.x == gridDim.x - 1 || blockIdx.y == gridDim.y - 1);

    float4 rA[4], rB[4], dA[4], dB[4];

    if (!border) {
        const float4* p4  = (const float4*)pin;
        const float4* dv4 = (const float4*)dv;
        int base = (gyBase * Wc + gx0) >> 2;
        const int rs = Wc >> 2;
        #pragma unroll
        for (int k = 0; k < 4; k++) {
            dA[k] = dv4[base + k * rs];
            dB[k] = dv4[base + k * rs + 1];
        }
        if (p_zero) {
            float4 z = make_float4(0.f, 0.f, 0.f, 0.f);
            #pragma unroll
            for (int k = 0; k < 4; k++) { rA[k] = z; rB[k] = z; }
        } else {
            #pragma unroll
            for (int k = 0; k < 4; k++) {
                rA[k] = p4[base + k * rs];
                rB[k] = p4[base + k * rs + 1];
            }
        }
    } else {
        #pragma unroll
        for (int k = 0; k < 4; k++) {
            int gy = gyBase + k;
            dA[k] = make_float4(gload(dv, gy, gx0),     gload(dv, gy, gx0 + 1),
                                gload(dv, gy, gx0 + 2), gload(dv, gy, gx0 + 3));
            dB[k] = make_float4(gload(dv, gy, gx0 + 4), gload(dv, gy, gx0 + 5),
                                gload(dv, gy, gx0 + 6), gload(dv, gy, gx0 + 7));
            if (p_zero) {
                rA[k] = make_float4(0.f, 0.f, 0.f, 0.f);
                rB[k] = rA[k];
            } else {
                rA[k] = make_float4(gload(pin, gy, gx0),     gload(pin, gy, gx0 + 1),
                                    gload(pin, gy, gx0 + 2), gload(pin, gy, gx0 + 3));
                rB[k] = make_float4(gload(pin, gy, gx0 + 4), gload(pin, gy, gx0 + 5),
                                    gload(pin, gy, gx0 + 6), gload(pin, gy, gx0 + 7));
            }
        }
    }

    bool rok[4];
    #pragma unroll
    for (int k = 0; k < 4; k++)
        rok[k] = (gyBase + k >= 1 && gyBase + k <= Hc - 2);
    bool okA0 = (gx0     >= 1 && gx0     <= Wc - 2);
    bool okA1 = (gx0 + 1 >= 1 && gx0 + 1 <= Wc - 2);
    bool okA2 = (gx0 + 2 >= 1 && gx0 + 2 <= Wc - 2);
    bool okA3 = (gx0 + 3 >= 1 && gx0 + 3 <= Wc - 2);
    bool okB0 = (gx0 + 4 >= 1 && gx0 + 4 <= Wc - 2);
    bool okB1 = (gx0 + 5 >= 1 && gx0 + 5 <= Wc - 2);
    bool okB2 = (gx0 + 6 >= 1 && gx0 + 6 <= Wc - 2);
    bool okB3 = (gx0 + 7 >= 1 && gx0 + 7 <= Wc - 2);

    const int tyUp = (ty == 0)  ? 0  : ty - 1;
    const int tyDn = (ty == 15) ? 15 : ty + 1;

    #pragma unroll
    for (int t = 0; t < 4; t++) {
        sTA[ty][tx] = rA[0];  sTB[ty][tx] = rB[0];
        sBA[ty][tx] = rA[3];  sBB[ty][tx] = rB[3];
        __syncthreads();
        float4 upA = sBA[tyUp][tx], upB = sBB[tyUp][tx];
        float4 dnA = sTA[tyDn][tx], dnB = sTB[tyDn][tx];
        __syncthreads();

        float4 prevA = upA, prevB = upB;
        #pragma unroll
        for (int k = 0; k < 4; k++) {
            float4 ceA = rA[k], ceB = rB[k];
            float4 belowA = (k == 3) ? dnA : rA[k + 1];
            float4 belowB = (k == 3) ? dnB : rB[k + 1];
            float lf = __shfl_up_sync(0xffffffffu, ceB.w, 1, 8);
            float rt = __shfl_down_sync(0xffffffffu, ceA.x, 1, 8);
            float4 oA, oB;
            oA.x = 0.25f * (prevA.x + belowA.x + lf    + ceA.y - dA[k].x);
            oA.y = 0.25f * (prevA.y + belowA.y + ceA.x + ceA.z - dA[k].y);
            oA.z = 0.25f * (prevA.z + belowA.z + ceA.y + ceA.w - dA[k].z);
            oA.w = 0.25f * (prevA.w + belowA.w + ceA.z + ceB.x - dA[k].w);
            oB.x = 0.25f * (prevB.x + belowB.x + ceA.w + ceB.y - dB[k].x);
            oB.y = 0.25f * (prevB.y + belowB.y + ceB.x + ceB.z - dB[k].y);
            oB.z = 0.25f * (prevB.z + belowB.z + ceB.y + ceB.w - dB[k].z);
            oB.w = 0.25f * (prevB.w + belowB.w + ceB.z + rt    - dB[k].w);
            if (border) {
                oA.x = (rok[k] && okA0) ? oA.x : 0.f;
                oA.y = (rok[k] && okA1) ? oA.y : 0.f;
                oA.z = (rok[k] && okA2) ? oA.z : 0.f;
                oA.w = (rok[k] && okA3) ? oA.w : 0.f;
                oB.x = (rok[k] && okB0) ? oB.x : 0.f;
                oB.y = (rok[k] && okB1) ? oB.y : 0.f;
                oB.z = (rok[k] && okB2) ? oB.z : 0.f;
                oB.w = (rok[k] && okB3) ? oB.w : 0.f;
            }
            rA[k] = oA; rB[k] = oB;
            prevA = ceA; prevB = ceB;
        }
    }

    // store central 56x56: tile cols [4,60) -> A if tx>=1, B if tx<7 (plus bounds)
    {
        bool stA = (tx >= 1) && (gx0 < Wc);
        bool stB = (tx < 7) && (gx0 + 4 < Wc);
        #pragma unroll
        for (int k = 0; k < 4; k++) {
            int trow = ty * 4 + k;
            if (trow >= 4 && trow < 60) {
                int gy = gyBase + k;
                if (gy < Hc) {
                    if (stA) *(float4*)&pout[gy * Wc + gx0] = rA[k];
                    if (stB) *(float4*)&pout[gy * Wc + gx0 + 4] = rB[k];
                }
            }
        }
    }
}

// ============ MEGA epilogue v3 (R15: projection-on-load, 4 smem arrays) ============
#define MT 48
#define MS 56
#define MROWS 52

__device__ __forceinline__ float tbilerp(const float* __restrict__ s, int oy, int ox,
                                         int clampH, int clampW, float y, float x) {
    int x0 = (int)floorf(x);
    int x1 = x0 + 1;
    int y0 = (int)floorf(y);
    int y1 = y0 + 1;
    x0 = min(max(x0, 0), clampW);
    x1 = min(max(x1, 0), clampW);
    y0 = min(max(y0, 0), clampH);
    y1 = min(max(y1, 0), clampH);
    float x0f = (float)x0, x1f = (float)x1;
    float y0f = (float)y0, y1f = (float)y1;
    float wa = (x1f - x) * (y1f - y);
    float wb = (x - x0f) * (y1f - y);
    float wc = (x1f - x) * (y - y0f);
    float wd = (x - x0f) * (y - y0f);
    int r0 = (y0 - oy) * MS, r1 = (y1 - oy) * MS;
    int c0 = x0 - ox, c1 = x1 - ox;
    return wa * s[r0 + c0] + wb * s[r0 + c1] + wc * s[r1 + c0] + wd * s[r1 + c1];
}

__device__ __forceinline__ float tbilerp_fast(const float* __restrict__ s, int oy, int ox,
                                              float y, float x) {
    int x0 = (int)floorf(x);
    int y0 = (int)floorf(y);
    float fx = x - (float)x0;
    float fy = y - (float)y0;
    int r0 = (y0 - oy) * MS;
    int c0 = x0 - ox;
    float a = s[r0 + c0], b = s[r0 + c0 + 1];
    float c = s[r0 + MS + c0], dd = s[r0 + MS + c0 + 1];
    float top = a + fx * (b - a);
    float bot = c + fx * (dd - c);
    return top + fy * (bot - top);
}

__global__ void __launch_bounds__(256)
mega_kernel(const float* __restrict__ u, const float* __restrict__ v,
            const float* __restrict__ p, const float* __restrict__ dens,
            float* __restrict__ out) {
    extern __shared__ float sm[];
    float* sU  = sm;
    float* sV  = sm + 1 * MROWS * MS;
    float* sD  = sm + 2 * MROWS * MS;
    float* sU2 = sm + 3 * MROWS * MS;
    float* sV2 = sU;

    const int tid = threadIdx.y * blockDim.x + threadIdx.x;
    const int by0 = blockIdx.y * MT;
    const int bx0 = blockIdx.x * MT;
    const int oy = by0 - 2, ox = bx0 - 4;
    const bool border = (blockIdx.x == 0 || blockIdx.y == 0 ||
                         blockIdx.x >= gridDim.x - 1 || blockIdx.y >= gridDim.y - 1);

    if (!border) {
        for (int idx = tid; idx < MROWS * 14; idx += 256) {
            int y = idx / 14, g = idx - y * 14;
            int gy = oy + y;
            int gx = ox + g * 4;
            float4 uu = *(const float4*)&u[gy * UW + gx];
            float4 pC = *(const float4*)&p[gy * Wc + gx];
            float4 pU = *(const float4*)&p[(gy - 1) * Wc + gx];
            float  pl = p[gy * Wc + gx - 1];
            const float* vr = &v[gy * VW + gx];
            float v0 = vr[0], v1 = vr[1], v2 = vr[2], v3 = vr[3];
            float4 dd = *(const float4*)&dens[gy * Wc + gx];
            int o = y * MS + g * 4;
            float4 up;
            up.x = uu.x - DT * (pC.x - pU.x);
            up.y = uu.y - DT * (pC.y - pU.y);
            up.z = uu.z - DT * (pC.z - pU.z);
            up.w = uu.w - DT * (pC.w - pU.w);
            *(float4*)&sU[o] = up;
            float4 vp;
            vp.x = v0 - DT * (pC.x - pl);
            vp.y = v1 - DT * (pC.y - pC.x);
            vp.z = v2 - DT * (pC.z - pC.y);
            vp.w = v3 - DT * (pC.w - pC.z);
            *(float4*)&sV[o] = vp;
            *(float4*)&sD[o] = dd;
        }
        __syncthreads();

        for (int idx = tid; idx < 49 * 49; idx += 256) {
            int yy = idx / 49, xx = idx - yy * 49;
            int gi = by0 + yy, gj = bx0 + xx;
            int o = (yy + 2) * MS + (xx + 4);
            float u_i = 0.5f * (sU[o] + sU[o + 1]);
            float v_i = 0.5f * (sV[o] + sV[o + MS]);
            float px = (float)gj - DT * u_i;
            float py = (float)gi - DT * v_i;
            sU2[yy * MS + xx] = tbilerp_fast(sU, oy, ox, py, px);
        }
        __syncthreads();

        for (int idx = tid; idx < 49 * MT; idx += 256) {
            int yy = idx / MT, xx = idx - yy * MT;
            int gi = by0 + yy, gj = bx0 + xx;
            int o2 = yy * MS + xx;
            int o = (yy + 2) * MS + (xx + 4);
            float u_i = 0.5f * (sU2[o2] + sU2[o2 + 1]);
            float v_i = 0.5f * (sV[o] + sV[o + MS]);
            float px = (float)gj - DT * u_i;
            float py = (float)gi - DT * v_i;
            sV2[o2] = tbilerp_fast(sV, oy, ox, py, px);
        }
        __syncthreads();

        for (int idx = tid; idx < MT * 12; idx += 256) {
            int yy = idx / 12, xq = idx - yy * 12;
            int gi = by0 + yy;
            int gj0 = bx0 + xq * 4;
            float res[4];
            #pragma unroll
            for (int e = 0; e < 4; e++) {
                int gj = gj0 + e;
                int o2 = yy * MS + (xq * 4 + e);
                float u_i = 0.5f * (sU2[o2] + sU2[o2 + 1]);
                float v_i = 0.5f * (sV2[o2] + sV2[o2 + MS]);
                float px = (float)gj - DT * u_i;
                float py = (float)gi - DT * v_i;
                res[e] = 0.995f * tbilerp_fast(sD, oy, ox, py, px);
            }
            *(float4*)&out[gi * Wc + gj0] = make_float4(res[0], res[1], res[2], res[3]);
        }
    } else {
        for (int idx = tid; idx < MROWS * MS; idx += 256) {
            int y = idx / MS, x = idx - y * MS;
            int gy = oy + y, gx = ox + x;
            float upv = 0.f, vpv = 0.f, dv = 0.f;
            if (gy >= 0 && gy < UH && gx >= 0 && gx < UW) {
                upv = u[gy * UW + gx];
                if (gy >= 1 && gy <= UH - 2)
                    upv -= DT * (gload(p, gy, gx) - gload(p, gy - 1, gx));
            }
            if (gy >= 0 && gy < VH && gx >= 0 && gx < VW) {
                vpv = v[gy * VW + gx];
                if (gx >= 1 && gx <= VW - 2)
                    vpv -= DT * (gload(p, gy, gx) - gload(p, gy, gx - 1));
            }
            if (gy >= 0 && gy < Hc && gx >= 0 && gx < Wc)
                dv = dens[gy * Wc + gx];
            int o = y * MS + x;
            sU[o] = upv; sV[o] = vpv; sD[o] = dv;
        }
        __syncthreads();

        for (int idx = tid; idx < 49 * 49; idx += 256) {
            int yy = idx / 49, xx = idx - yy * 49;
            int gi = by0 + yy, gj = bx0 + xx;
            float val = 0.f;
            if (gi <= UH - 1 && gj <= UW - 1) {
                int o = (gi - oy) * MS + (gj - ox);
                float u_i = (gj < UW - 1) ? 0.5f * (sU[o] + sU[o + 1]) : 0.0f;
                float v_i = (gi < VH - 1) ? 0.5f * (sV[o] + sV[o + MS]) : 0.0f;
                float px = fminf(fmaxf((float)gj - DT * u_i, 0.0f), (float)(UW - 1));
                float py = fminf(fmaxf((float)gi - DT * v_i, 0.0f), (float)(UH - 1));
                val = tbilerp(sU, oy, ox, UH - 1, UW - 1, py, px);
            }
            sU2[yy * MS + xx] = val;
        }
        __syncthreads();

        for (int idx = tid; idx < 49 * MT; idx += 256) {
            int yy = idx / MT, xx = idx - yy * MT;
            int gi = by0 + yy, gj = bx0 + xx;
            float val = 0.f;
            if (gi <= VH - 1 && gj <= VW - 1) {
                int o2 = yy * MS + xx;
                int o = (gi - oy) * MS + (gj - ox);
                float u_i = (gj < UW - 1) ? 0.5f * (sU2[o2] + sU2[o2 + 1]) : 0.0f;
                float v_i = (gi < VH - 1) ? 0.5f * (sV[o] + sV[o + MS]) : 0.0f;
                float px = fminf(fmaxf((float)gj - DT * u_i, 0.0f), (float)(VW - 1));
                float py = fminf(fmaxf((float)gi - DT * v_i, 0.0f), (float)(VH - 1));
                val = tbilerp(sV, oy, ox, VH - 1, VW - 1, py, px);
            }
            sV2[yy * MS + xx] = val;
        }
        __syncthreads();

        for (int idx = tid; idx < MT * 12; idx += 256) {
            int yy = idx / 12, xq = idx - yy * 12;
            int gi = by0 + yy;
            int gj0 = bx0 + xq * 4;
            if (gi > Hc - 1) continue;
            float res[4];
            #pragma unroll
            for (int e = 0; e < 4; e++) {
                int gj = gj0 + e;
                res[e] = 0.f;
                if (gj <= Wc - 1) {
                    int o2 = yy * MS + (xq * 4 + e);
                    float u_i = (gj < UW - 1) ? 0.5f * (sU2[o2] + sU2[o2 + 1]) : 0.0f;
                    float v_i = (gi < VH - 1) ? 0.5f * (sV2[o2] + sV2[o2 + MS]) : 0.0f;
                    float px = fminf(fmaxf((float)gj - DT * u_i, 0.0f), (float)(Wc - 1));
                    float py = fminf(fmaxf((float)gi - DT * v_i, 0.0f), (float)(Hc - 1));
                    res[e] = 0.995f * tbilerp(sD, oy, ox, Hc - 1, Wc - 1, py, px);
                }
            }
            if (gj0 + 3 <= Wc - 1) {
                *(float4*)&out[gi * Wc + gj0] = make_float4(res[0], res[1], res[2], res[3]);
            } else {
                #pragma unroll
                for (int e = 0; e < 4; e++)
                    if (gj0 + e <= Wc - 1) out[gi * Wc + gj0 + e] = res[e];
            }
        }
    }
}

extern "C" void kernel_launch(void* const* d_in, const int* in_sizes, int n_in,
                              void* d_out, int out_size) {
    const float* u_in    = (const float*)d_in[0];
    const float* v_in    = (const float*)d_in[1];
    const float* dens_in = (const float*)d_in[2];
    float* out = (float*)d_out;

    float *du, *dv_, *dd, *ddiv, *dp, *dp2;
    cudaGetSymbolAddress((void**)&du,   g_u);
    cudaGetSymbolAddress((void**)&dv_,  g_v);
    cudaGetSymbolAddress((void**)&dd,   g_dens);
    cudaGetSymbolAddress((void**)&ddiv, g_div);
    cudaGetSymbolAddress((void**)&dp,   g_p);
    cudaGetSymbolAddress((void**)&dp2,  g_p2);

    int w4 = Wc >> 2;
    dim3 blkQ(64, 4);
    dim3 grdQ_S((w4 + 63) / 64, (Hc + 3) / 4);

    // 1. fused diffuse
    {
        dim3 grdD((w4 + 63) / 64, (UH + 3) / 4, 3);
        diffuse_all_kernel<<<grdD, blkQ>>>(u_in, v_in, dens_in, du, dv_, dd);
    }

    // 2. divergence
    div_f4_kernel<<<grdQ_S, blkQ>>>(du, dv_, ddiv);

    // 3. 20 Jacobi iterations = 5 fused x4 launches (wide strips, half shfl)
    {
        dim3 blkJ(8, 16);
        int gj = (Hc + OT - 1) / OT;   // 37
        dim3 grdJ(gj, gj);
        jacobiW_kernel<<<grdJ, blkJ>>>(dp2, ddiv, dp, 1);
        jacobiW_kernel<<<grdJ, blkJ>>>(dp, ddiv, dp2, 0);
        jacobiW_kernel<<<grdJ, blkJ>>>(dp2, ddiv, dp, 0);
        jacobiW_kernel<<<grdJ, blkJ>>>(dp, ddiv, dp2, 0);
        jacobiW_kernel<<<grdJ, blkJ>>>(dp2, ddiv, dp, 0);   // -> dp
    }

    // 4. MEGA v3
    {
        int msmem = 4 * MROWS * MS * (int)sizeof(float);   // 46.6 KB
        static int attr_set = 0;
        if (!attr_set) {
            cudaFuncSetAttribute(mega_kernel,
                                 cudaFuncAttributeMaxDynamicSharedMemorySize, msmem);
            attr_set = 1;
        }
        dim3 blkM(16, 16);
        int gm = (Hc + MT - 1) / MT;   // 43
        dim3 grdM(gm, gm);
        mega_kernel<<<grdM, blkM, msmem>>>(du, dv_, dp, dd, out);
    }
}

// round 17
// speedup vs baseline: 1.1141x; 1.1141x over previous
#include <cuda_runtime.h>

#define Hc 2048
#define Wc 2048
#define UH 2049
#define UW 2048
#define VH 2048
#define VW 2049
#define DT 0.01f
#define VISC 0.001f

// Device scratch
__device__ float g_u  [UH * UW];
__device__ float g_v  [VH * VW];
__device__ float g_dens[Hc * Wc];
__device__ float g_div [Hc * Wc];
__device__ float g_p  [Hc * Wc];
__device__ float g_p2 [Hc * Wc];

// ================= fused diffuse (u | v+force | dens) =================
__device__ __forceinline__ void diffuse_f4_body(const float* __restrict__ f,
                                                float* __restrict__ out,
                                                int h, int w, float a,
                                                int qx, int i) {
    int w4 = w >> 2;
    if (i >= h || qx >= w4) return;
    int j0 = qx * 4;
    const float4* f4 = (const float4*)f;
    float4 c  = f4[i * w4 + qx];
    int iu = max(i - 1, 0), id = min(i + 1, h - 1);
    float4 up = f4[iu * w4 + qx];
    float4 dn = f4[id * w4 + qx];
    float lf = (j0 > 0)       ? f[i * w + j0 - 1] : c.x;
    float rt = (j0 + 4 < w)   ? f[i * w + j0 + 4] : c.w;
    float4 r;
    r.x = c.x + a * (up.x + dn.x + lf  + c.y - 4.0f * c.x);
    r.y = c.y + a * (up.y + dn.y + c.x + c.z - 4.0f * c.y);
    r.z = c.z + a * (up.z + dn.z + c.y + c.w - 4.0f * c.z);
    r.w = c.w + a * (up.w + dn.w + c.z + rt  - 4.0f * c.w);
    ((float4*)out)[i * w4 + qx] = r;
}

__device__ __forceinline__ float vfrc(const float* __restrict__ v,
                                      const float* __restrict__ dens,
                                      int i, int j) {
    float val = v[i * VW + j];
    if (j < Wc) val += (DT * 0.1f) * dens[i * Wc + j];
    return val;
}

__device__ __forceinline__ float4 vfrc4s(const float* __restrict__ v,
                                         const float* __restrict__ dens,
                                         int i, int j0) {
    const float* vr = &v[i * VW + j0];
    float4 val = make_float4(vr[0], vr[1], vr[2], vr[3]);
    float4 dd  = *(const float4*)&dens[i * Wc + j0];
    val.x += (DT * 0.1f) * dd.x;
    val.y += (DT * 0.1f) * dd.y;
    val.z += (DT * 0.1f) * dd.z;
    val.w += (DT * 0.1f) * dd.w;
    return val;
}

__global__ void diffuse_all_kernel(const float* __restrict__ u_in,
                                   const float* __restrict__ v_in,
                                   const float* __restrict__ dens_in,
                                   float* __restrict__ u_out,
                                   float* __restrict__ v_out,
                                   float* __restrict__ dens_out) {
    int qx = blockIdx.x * blockDim.x + threadIdx.x;
    int i  = blockIdx.y * blockDim.y + threadIdx.y;
    int z  = blockIdx.z;
    const float a  = DT * VISC;
    const float ad = DT * VISC * 0.1f;

    if (z == 0) {
        diffuse_f4_body(u_in, u_out, UH, UW, a, qx, i);
    } else if (z == 2) {
        diffuse_f4_body(dens_in, dens_out, Hc, Wc, ad, qx, i);
    } else {
        if (i >= VH || qx >= 512) return;
        int j0 = qx * 4;
        int iu = max(i - 1, 0), id = min(i + 1, VH - 1);
        float4 c  = vfrc4s(v_in, dens_in, i, j0);
        float4 up = vfrc4s(v_in, dens_in, iu, j0);
        float4 dn = vfrc4s(v_in, dens_in, id, j0);
        float lf = (j0 > 0) ? vfrc(v_in, dens_in, i, j0 - 1) : c.x;
        float rt = vfrc(v_in, dens_in, i, j0 + 4);
        float4 r;
        r.x = c.x + a * (up.x + dn.x + lf  + c.y - 4.0f * c.x);
        r.y = c.y + a * (up.y + dn.y + c.x + c.z - 4.0f * c.y);
        r.z = c.z + a * (up.z + dn.z + c.y + c.w - 4.0f * c.z);
        r.w = c.w + a * (up.w + dn.w + c.z + rt  - 4.0f * c.w);
        float* vo = &v_out[i * VW + j0];
        vo[0] = r.x; vo[1] = r.y; vo[2] = r.z; vo[3] = r.w;
        if (qx == 511) {
            int j = 2048;
            float cc = v_in[i * VW + j];
            float u2 = v_in[iu * VW + j];
            float d2 = v_in[id * VW + j];
            float l2 = vfrc(v_in, dens_in, i, j - 1);
            v_out[i * VW + j] = cc + a * (u2 + d2 + l2 + cc - 4.0f * cc);
        }
    }
}

// ---- divergence ----
__global__ void div_f4_kernel(const float* __restrict__ u, const float* __restrict__ v,
                              float* __restrict__ dv) {
    int qx = blockIdx.x * blockDim.x + threadIdx.x;
    int i  = blockIdx.y * blockDim.y + threadIdx.y;
    int w4 = Wc >> 2;
    if (i >= Hc || qx >= w4) return;
    int j0 = qx * 4;
    const float4* u4 = (const float4*)u;
    float4 u0 = u4[i * w4 + qx];
    float4 u1 = u4[(i + 1) * w4 + qx];
    const float* vr = v + i * VW + j0;
    float v0 = vr[0], v1 = vr[1], v2 = vr[2], v3 = vr[3], v4 = vr[4];
    float4 r;
    r.x = (u1.x - u0.x + v1 - v0) / DT;
    r.y = (u1.y - u0.y + v2 - v1) / DT;
    r.z = (u1.z - u0.z + v3 - v2) / DT;
    r.w = (u1.w - u0.w + v4 - v3) / DT;
    ((float4*)dv)[i * w4 + qx] = r;
}

// ============ fused JT-iteration Jacobi, R9 inner structure, template halo ============
__device__ __forceinline__ float gload(const float* __restrict__ p, int gy, int gx) {
    return (gy >= 0 && gy < Hc && gx >= 0 && gx < Wc) ? p[gy * Wc + gx] : 0.0f;
}

template<int JT, int OTl>
__global__ void __launch_bounds__(256)
jacobiT_kernel(const float* __restrict__ pin, const float* __restrict__ dv,
               float* __restrict__ pout, int p_zero) {
    __shared__ float4 sTop[16][17];
    __shared__ float4 sBot[16][17];

    const int tx = threadIdx.x;
    const int ty = threadIdx.y;
    const int bx0 = blockIdx.x * OTl - JT;
    const int by0 = blockIdx.y * OTl - JT;
    const int gx0 = bx0 + tx * 4;
    const int gyBase = by0 + ty * 4;
    const bool border = (blockIdx.x == 0 || blockIdx.y == 0 ||
                         blockIdx.x == gridDim.x - 1 || blockIdx.y == gridDim.y - 1);

    float4 r[4], d[4];

    if (!border) {
        const float4* p4  = (const float4*)pin;
        const float4* dv4 = (const float4*)dv;
        int base = (gyBase * Wc + gx0) >> 2;
        const int rs = Wc >> 2;
        #pragma unroll
        for (int k = 0; k < 4; k++) d[k] = dv4[base + k * rs];
        if (p_zero) {
            float4 z = make_float4(0.f, 0.f, 0.f, 0.f);
            #pragma unroll
            for (int k = 0; k < 4; k++) r[k] = z;
        } else {
            #pragma unroll
            for (int k = 0; k < 4; k++) r[k] = p4[base + k * rs];
        }
    } else {
        #pragma unroll
        for (int k = 0; k < 4; k++) {
            int gy = gyBase + k;
            d[k] = make_float4(gload(dv, gy, gx0),     gload(dv, gy, gx0 + 1),
                               gload(dv, gy, gx0 + 2), gload(dv, gy, gx0 + 3));
            if (p_zero) r[k] = make_float4(0.f, 0.f, 0.f, 0.f);
            else        r[k] = make_float4(gload(pin, gy, gx0),     gload(pin, gy, gx0 + 1),
                                           gload(pin, gy, gx0 + 2), gload(pin, gy, gx0 + 3));
        }
    }

    bool rok[4];
    bool ok0 = (gx0     >= 1 && gx0     <= Wc - 2);
    bool ok1 = (gx0 + 1 >= 1 && gx0 + 1 <= Wc - 2);
    bool ok2 = (gx0 + 2 >= 1 && gx0 + 2 <= Wc - 2);
    bool ok3 = (gx0 + 3 >= 1 && gx0 + 3 <= Wc - 2);
    #pragma unroll
    for (int k = 0; k < 4; k++)
        rok[k] = (gyBase + k >= 1 && gyBase + k <= Hc - 2);

    const int tyUp = (ty == 0)  ? 0  : ty - 1;
    const int tyDn = (ty == 15) ? 15 : ty + 1;

    #pragma unroll
    for (int t = 0; t < JT; t++) {
        sTop[ty][tx] = r[0];
        sBot[ty][tx] = r[3];
        __syncthreads();
        float4 up = sBot[tyUp][tx];
        float4 dn = sTop[tyDn][tx];
        __syncthreads();

        float4 prev = up;
        #pragma unroll
        for (int k = 0; k < 4; k++) {
            float4 ce = r[k];
            float4 below = (k == 3) ? dn : r[k + 1];
            float lf = __shfl_up_sync(0xffffffffu, ce.w, 1, 16);
            float rt = __shfl_down_sync(0xffffffffu, ce.x, 1, 16);
            float4 o;
            o.x = 0.25f * (prev.x + below.x + lf   + ce.y - d[k].x);
            o.y = 0.25f * (prev.y + below.y + ce.x + ce.z - d[k].y);
            o.z = 0.25f * (prev.z + below.z + ce.y + ce.w - d[k].z);
            o.w = 0.25f * (prev.w + below.w + ce.z + rt   - d[k].w);
            if (border) {
                o.x = (rok[k] && ok0) ? o.x : 0.f;
                o.y = (rok[k] && ok1) ? o.y : 0.f;
                o.z = (rok[k] && ok2) ? o.z : 0.f;
                o.w = (rok[k] && ok3) ? o.w : 0.f;
            }
            r[k] = o;
            prev = ce;
        }
    }

    if (tx >= (JT / 4) && tx < 16 - (JT / 4) && gx0 < Wc) {
        #pragma unroll
        for (int k = 0; k < 4; k++) {
            int trow = ty * 4 + k;
            if (trow >= JT && trow < 64 - JT) {
                int gy = gyBase + k;
                if (gy < Hc)
                    *(float4*)&pout[gy * Wc + gx0] = r[k];
            }
        }
    }
}

// ============ MEGA epilogue v3 (R15: projection-on-load, 4 smem arrays) ============
#define MT 48
#define MS 56
#define MROWS 52

__device__ __forceinline__ float tbilerp(const float* __restrict__ s, int oy, int ox,
                                         int clampH, int clampW, float y, float x) {
    int x0 = (int)floorf(x);
    int x1 = x0 + 1;
    int y0 = (int)floorf(y);
    int y1 = y0 + 1;
    x0 = min(max(x0, 0), clampW);
    x1 = min(max(x1, 0), clampW);
    y0 = min(max(y0, 0), clampH);
    y1 = min(max(y1, 0), clampH);
    float x0f = (float)x0, x1f = (float)x1;
    float y0f = (float)y0, y1f = (float)y1;
    float wa = (x1f - x) * (y1f - y);
    float wb = (x - x0f) * (y1f - y);
    float wc = (x1f - x) * (y - y0f);
    float wd = (x - x0f) * (y - y0f);
    int r0 = (y0 - oy) * MS, r1 = (y1 - oy) * MS;
    int c0 = x0 - ox, c1 = x1 - ox;
    return wa * s[r0 + c0] + wb * s[r0 + c1] + wc * s[r1 + c0] + wd * s[r1 + c1];
}

__device__ __forceinline__ float tbilerp_fast(const float* __restrict__ s, int oy, int ox,
                                              float y, float x) {
    int x0 = (int)floorf(x);
    int y0 = (int)floorf(y);
    float fx = x - (float)x0;
    float fy = y - (float)y0;
    int r0 = (y0 - oy) * MS;
    int c0 = x0 - ox;
    float a = s[r0 + c0], b = s[r0 + c0 + 1];
    float c = s[r0 + MS + c0], dd = s[r0 + MS + c0 + 1];
    float top = a + fx * (b - a);
    float bot = c + fx * (dd - c);
    return top + fy * (bot - top);
}

__global__ void __launch_bounds__(256)
mega_kernel(const float* __restrict__ u, const float* __restrict__ v,
            const float* __restrict__ p, const float* __restrict__ dens,
            float* __restrict__ out) {
    extern __shared__ float sm[];
    float* sU  = sm;
    float* sV  = sm + 1 * MROWS * MS;
    float* sD  = sm + 2 * MROWS * MS;
    float* sU2 = sm + 3 * MROWS * MS;
    float* sV2 = sU;

    const int tid = threadIdx.y * blockDim.x + threadIdx.x;
    const int by0 = blockIdx.y * MT;
    const int bx0 = blockIdx.x * MT;
    const int oy = by0 - 2, ox = bx0 - 4;
    const bool border = (blockIdx.x == 0 || blockIdx.y == 0 ||
                         blockIdx.x >= gridDim.x - 1 || blockIdx.y >= gridDim.y - 1);

    if (!border) {
        for (int idx = tid; idx < MROWS * 14; idx += 256) {
            int y = idx / 14, g = idx - y * 14;
            int gy = oy + y;
            int gx = ox + g * 4;
            float4 uu = *(const float4*)&u[gy * UW + gx];
            float4 pC = *(const float4*)&p[gy * Wc + gx];
            float4 pU = *(const float4*)&p[(gy - 1) * Wc + gx];
            float  pl = p[gy * Wc + gx - 1];
            const float* vr = &v[gy * VW + gx];
            float v0 = vr[0], v1 = vr[1], v2 = vr[2], v3 = vr[3];
            float4 dd = *(const float4*)&dens[gy * Wc + gx];
            int o = y * MS + g * 4;
            float4 up;
            up.x = uu.x - DT * (pC.x - pU.x);
            up.y = uu.y - DT * (pC.y - pU.y);
            up.z = uu.z - DT * (pC.z - pU.z);
            up.w = uu.w - DT * (pC.w - pU.w);
            *(float4*)&sU[o] = up;
            float4 vp;
            vp.x = v0 - DT * (pC.x - pl);
            vp.y = v1 - DT * (pC.y - pC.x);
            vp.z = v2 - DT * (pC.z - pC.y);
            vp.w = v3 - DT * (pC.w - pC.z);
            *(float4*)&sV[o] = vp;
            *(float4*)&sD[o] = dd;
        }
        __syncthreads();

        for (int idx = tid; idx < 49 * 49; idx += 256) {
            int yy = idx / 49, xx = idx - yy * 49;
            int gi = by0 + yy, gj = bx0 + xx;
            int o = (yy + 2) * MS + (xx + 4);
            float u_i = 0.5f * (sU[o] + sU[o + 1]);
            float v_i = 0.5f * (sV[o] + sV[o + MS]);
            float px = (float)gj - DT * u_i;
            float py = (float)gi - DT * v_i;
            sU2[yy * MS + xx] = tbilerp_fast(sU, oy, ox, py, px);
        }
        __syncthreads();

        for (int idx = tid; idx < 49 * MT; idx += 256) {
            int yy = idx / MT, xx = idx - yy * MT;
            int gi = by0 + yy, gj = bx0 + xx;
            int o2 = yy * MS + xx;
            int o = (yy + 2) * MS + (xx + 4);
            float u_i = 0.5f * (sU2[o2] + sU2[o2 + 1]);
            float v_i = 0.5f * (sV[o] + sV[o + MS]);
            float px = (float)gj - DT * u_i;
            float py = (float)gi - DT * v_i;
            sV2[o2] = tbilerp_fast(sV, oy, ox, py, px);
        }
        __syncthreads();

        for (int idx = tid; idx < MT * 12; idx += 256) {
            int yy = idx / 12, xq = idx - yy * 12;
            int gi = by0 + yy;
            int gj0 = bx0 + xq * 4;
            float res[4];
            #pragma unroll
            for (int e = 0; e < 4; e++) {
                int gj = gj0 + e;
                int o2 = yy * MS + (xq * 4 + e);
                float u_i = 0.5f * (sU2[o2] + sU2[o2 + 1]);
                float v_i = 0.5f * (sV2[o2] + sV2[o2 + MS]);
                float px = (float)gj - DT * u_i;
                float py = (float)gi - DT * v_i;
                res[e] = 0.995f * tbilerp_fast(sD, oy, ox, py, px);
            }
            *(float4*)&out[gi * Wc + gj0] = make_float4(res[0], res[1], res[2], res[3]);
        }
    } else {
        for (int idx = tid; idx < MROWS * MS; idx += 256) {
            int y = idx / MS, x = idx - y * MS;
            int gy = oy + y, gx = ox + x;
            float upv = 0.f, vpv = 0.f, dv = 0.f;
            if (gy >= 0 && gy < UH && gx >= 0 && gx < UW) {
                upv = u[gy * UW + gx];
                if (gy >= 1 && gy <= UH - 2)
                    upv -= DT * (gload(p, gy, gx) - gload(p, gy - 1, gx));
            }
            if (gy >= 0 && gy < VH && gx >= 0 && gx < VW) {
                vpv = v[gy * VW + gx];
                if (gx >= 1 && gx <= VW - 2)
                    vpv -= DT * (gload(p, gy, gx) - gload(p, gy, gx - 1));
            }
            if (gy >= 0 && gy < Hc && gx >= 0 && gx < Wc)
                dv = dens[gy * Wc + gx];
            int o = y * MS + x;
            sU[o] = upv; sV[o] = vpv; sD[o] = dv;
        }
        __syncthreads();

        for (int idx = tid; idx < 49 * 49; idx += 256) {
            int yy = idx / 49, xx = idx - yy * 49;
            int gi = by0 + yy, gj = bx0 + xx;
            float val = 0.f;
            if (gi <= UH - 1 && gj <= UW - 1) {
                int o = (gi - oy) * MS + (gj - ox);
                float u_i = (gj < UW - 1) ? 0.5f * (sU[o] + sU[o + 1]) : 0.0f;
                float v_i = (gi < VH - 1) ? 0.5f * (sV[o] + sV[o + MS]) : 0.0f;
                float px = fminf(fmaxf((float)gj - DT * u_i, 0.0f), (float)(UW - 1));
                float py = fminf(fmaxf((float)gi - DT * v_i, 0.0f), (float)(UH - 1));
                val = tbilerp(sU, oy, ox, UH - 1, UW - 1, py, px);
            }
            sU2[yy * MS + xx] = val;
        }
        __syncthreads();

        for (int idx = tid; idx < 49 * MT; idx += 256) {
            int yy = idx / MT, xx = idx - yy * MT;
            int gi = by0 + yy, gj = bx0 + xx;
            float val = 0.f;
            if (gi <= VH - 1 && gj <= VW - 1) {
                int o2 = yy * MS + xx;
                int o = (gi - oy) * MS + (gj - ox);
                float u_i = (gj < UW - 1) ? 0.5f * (sU2[o2] + sU2[o2 + 1]) : 0.0f;
                float v_i = (gi < VH - 1) ? 0.5f * (sV[o] + sV[o + MS]) : 0.0f;
                float px = fminf(fmaxf((float)gj - DT * u_i, 0.0f), (float)(VW - 1));
                float py = fminf(fmaxf((float)gi - DT * v_i, 0.0f), (float)(VH - 1));
                val = tbilerp(sV, oy, ox, VH - 1, VW - 1, py, px);
            }
            sV2[yy * MS + xx] = val;
        }
        __syncthreads();

        for (int idx = tid; idx < MT * 12; idx += 256) {
            int yy = idx / 12, xq = idx - yy * 12;
            int gi = by0 + yy;
            int gj0 = bx0 + xq * 4;
            if (gi > Hc - 1) continue;
            float res[4];
            #pragma unroll
            for (int e = 0; e < 4; e++) {
                int gj = gj0 + e;
                res[e] = 0.f;
                if (gj <= Wc - 1) {
                    int o2 = yy * MS + (xq * 4 + e);
                    float u_i = (gj < UW - 1) ? 0.5f * (sU2[o2] + sU2[o2 + 1]) : 0.0f;
                    float v_i = (gi < VH - 1) ? 0.5f * (sV2[o2] + sV2[o2 + MS]) : 0.0f;
                    float px = fminf(fmaxf((float)gj - DT * u_i, 0.0f), (float)(Wc - 1));
                    float py = fminf(fmaxf((float)gi - DT * v_i, 0.0f), (float)(Hc - 1));
                    res[e] = 0.995f * tbilerp(sD, oy, ox, Hc - 1, Wc - 1, py, px);
                }
            }
            if (gj0 + 3 <= Wc - 1) {
                *(float4*)&out[gi * Wc + gj0] = make_float4(res[0], res[1], res[2], res[3]);
            } else {
                #pragma unroll
                for (int e = 0; e < 4; e++)
                    if (gj0 + e <= Wc - 1) out[gi * Wc + gj0 + e] = res[e];
            }
        }
    }
}

extern "C" void kernel_launch(void* const* d_in, const int* in_sizes, int n_in,
                              void* d_out, int out_size) {
    const float* u_in    = (const float*)d_in[0];
    const float* v_in    = (const float*)d_in[1];
    const float* dens_in = (const float*)d_in[2];
    float* out = (float*)d_out;

    float *du, *dv_, *dd, *ddiv, *dp, *dp2;
    cudaGetSymbolAddress((void**)&du,   g_u);
    cudaGetSymbolAddress((void**)&dv_,  g_v);
    cudaGetSymbolAddress((void**)&dd,   g_dens);
    cudaGetSymbolAddress((void**)&ddiv, g_div);
    cudaGetSymbolAddress((void**)&dp,   g_p);
    cudaGetSymbolAddress((void**)&dp2,  g_p2);

    int w4 = Wc >> 2;
    dim3 blkQ(64, 4);
    dim3 grdQ_S((w4 + 63) / 64, (Hc + 3) / 4);

    // 1. fused diffuse
    {
        dim3 grdD((w4 + 63) / 64, (UH + 3) / 4, 3);
        diffuse_all_kernel<<<grdD, blkQ>>>(u_in, v_in, dens_in, du, dv_, dd);
    }

    // 2. divergence
    div_f4_kernel<<<grdQ_S, blkQ>>>(du, dv_, ddiv);

    // 3. 20 Jacobi iterations = 8 + 8 + 4 in 3 launches
    {
        dim3 blkJ(16, 16);
        int g8 = (Hc + 47) / 48;   // 43
        int g4 = (Hc + 55) / 56;   // 37
        dim3 grdJ8(g8, g8), grdJ4(g4, g4);
        jacobiT_kernel<8, 48><<<grdJ8, blkJ>>>(dp2, ddiv, dp, 1);   // iters 1-8 (p0=0)
        jacobiT_kernel<8, 48><<<grdJ8, blkJ>>>(dp, ddiv, dp2, 0);   // 9-16
        jacobiT_kernel<4, 56><<<grdJ4, blkJ>>>(dp2, ddiv, dp, 0);   // 17-20 -> dp
    }

    // 4. MEGA v3
    {
        int msmem = 4 * MROWS * MS * (int)sizeof(float);   // 46.6 KB
        static int attr_set = 0;
        if (!attr_set) {
            cudaFuncSetAttribute(mega_kernel,
                                 cudaFuncAttributeMaxDynamicSharedMemorySize, msmem);
            attr_set = 1;
        }
        dim3 blkM(16, 16);
        int gm = (Hc + MT - 1) / MT;   // 43
        dim3 grdM(gm, gm);
        mega_kernel<<<grdM, blkM, msmem>>>(du, dv_, dp, dd, out);
    }
}